// round 6
// baseline (speedup 1.0000x reference)
#include <cuda_runtime.h>
#include <cuda_bf16.h>
#include <cstdint>

// PairwiseRepresentation: masked periodic pairwise distances.
//   positions      [B,N,3]   f32
//   neighbors      [B,N,K]   i32
//   neighbor_mask  [B,N,K]   f32
//   cell           [B,3,3]   f32
//   cell_offsets   [B,N,K,3] f32
//   out            [B,N,K]   f32
//
// R6: LDG streaming is capped ~4.5TB/s by the per-SM L1TEX wavefront queue
// (~248 entries x DRAM latency). Escape it: stream neighbors/mask/offsets
// with cp.async.bulk (TMA engine, own buffering, ~11TB/s chip path) into a
// 4-stage smem ring. Gathers stay in a 64KB smem position table.

// ---------------- PTX helpers ----------------
__device__ __forceinline__ uint32_t smem_u32(const void* p) {
    return (uint32_t)__cvta_generic_to_shared(p);
}
__device__ __forceinline__ void mbar_init(uint32_t a, uint32_t cnt) {
    asm volatile("mbarrier.init.shared.b64 [%0], %1;" :: "r"(a), "r"(cnt) : "memory");
}
__device__ __forceinline__ void mbar_expect_tx(uint32_t a, uint32_t bytes) {
    asm volatile("mbarrier.arrive.expect_tx.shared.b64 _, [%0], %1;"
                 :: "r"(a), "r"(bytes) : "memory");
}
__device__ __forceinline__ void mbar_arrive(uint32_t a) {
    asm volatile("mbarrier.arrive.shared.b64 _, [%0];" :: "r"(a) : "memory");
}
__device__ __forceinline__ void mbar_wait(uint32_t a, uint32_t parity) {
    uint32_t done;
    asm volatile("{\n\t.reg .pred p;\n\t"
                 "mbarrier.try_wait.parity.acquire.cta.shared::cta.b64 p, [%1], %2;\n\t"
                 "selp.b32 %0, 1, 0, p;\n\t}"
                 : "=r"(done) : "r"(a), "r"(parity) : "memory");
    while (!done) {
        asm volatile("{\n\t.reg .pred p;\n\t"
                     "mbarrier.try_wait.parity.acquire.cta.shared::cta.b64 p, [%1], %2, 0x989680;\n\t"
                     "selp.b32 %0, 1, 0, p;\n\t}"
                     : "=r"(done) : "r"(a), "r"(parity) : "memory");
    }
}
__device__ __forceinline__ void bulk_g2s(uint32_t dst, const void* src,
                                         uint32_t bytes, uint32_t mbar) {
    asm volatile(
        "cp.async.bulk.shared::cluster.global.mbarrier::complete_tx::bytes "
        "[%0], [%1], %2, [%3];"
        :: "r"(dst), "l"(src), "r"(bytes), "r"(mbar) : "memory");
}

// ---------------- TMA-streamed main kernel (K == 128) ----------------
#define TK           128
#define STAGES       4
#define ROWS_PER_CH  4
#define STAGE_BYTES  (ROWS_PER_CH * (512 + 512 + 1536))   // 10240
#define ST_NB        0
#define ST_MK        (ROWS_PER_CH * 512)                   // 2048
#define ST_OFF       (ROWS_PER_CH * 1024)                  // 4096

__global__ __launch_bounds__(256, 2)
void pairwise_tma_kernel(const float*  __restrict__ positions,
                         const int*    __restrict__ neighbors,
                         const float*  __restrict__ mask,
                         const float*  __restrict__ cell,
                         const float*  __restrict__ offsets,
                         float*        __restrict__ out,
                         int N, int rowsPer)
{
    extern __shared__ char smem_raw[];
    float4*  s_tab   = (float4*)smem_raw;                       // N*16 B
    char*    s_stage = smem_raw + (size_t)N * 16;               // 4*10240 B
    uint64_t* bar    = (uint64_t*)(s_stage + STAGES * STAGE_BYTES); // 8 mbarriers

    const int b    = blockIdx.y;
    const int tid  = threadIdx.x;
    const int warp = tid >> 5;
    const int lane = tid & 31;

    const int r0 = blockIdx.x * rowsPer;
    const int r1 = min(r0 + rowsPer, N);
    const int nChunks = (r1 > r0) ? ((r1 - r0 + ROWS_PER_CH - 1) / ROWS_PER_CH) : 0;

    const uint32_t stage_a = smem_u32(s_stage);

    if (tid == 0) {
        #pragma unroll
        for (int s = 0; s < STAGES; ++s) {
            mbar_init(smem_u32(bar + s), 1);            // full: 1 arrive (expect_tx)
            mbar_init(smem_u32(bar + STAGES + s), 256); // empty: all threads
        }
    }
    __syncthreads();

    // Prologue: issue first STAGES-1 chunks (thread 0 only).
    if (tid == 0) {
        for (int j = 0; j < STAGES - 1 && j < nChunks; ++j) {
            const int rBase = r0 + j * ROWS_PER_CH;
            const int rows  = min(ROWS_PER_CH, r1 - rBase);
            const uint32_t fb = smem_u32(bar + j);
            mbar_expect_tx(fb, (uint32_t)rows * 2560u);
            const size_t g = (size_t)b * N + rBase;
            const uint32_t dst = stage_a + j * STAGE_BYTES;
            bulk_g2s(dst + ST_NB,  neighbors + g * TK,     rows * 512,  fb);
            bulk_g2s(dst + ST_MK,  mask      + g * TK,     rows * 512,  fb);
            bulk_g2s(dst + ST_OFF, offsets   + g * TK * 3, rows * 1536, fb);
        }
    }

    // Fill the position table (overlaps with in-flight TMA).
    const float* pb = positions + (size_t)b * N * 3;
    for (int i = tid; i < N; i += blockDim.x)
        s_tab[i] = make_float4(__ldg(&pb[i * 3 + 0]),
                               __ldg(&pb[i * 3 + 1]),
                               __ldg(&pb[i * 3 + 2]), 0.0f);

    const float* cbp = cell + b * 9;
    const float c00 = __ldg(&cbp[0]), c01 = __ldg(&cbp[1]), c02 = __ldg(&cbp[2]);
    const float c10 = __ldg(&cbp[3]), c11 = __ldg(&cbp[4]), c12 = __ldg(&cbp[5]);
    const float c20 = __ldg(&cbp[6]), c21 = __ldg(&cbp[7]), c22 = __ldg(&cbp[8]);

    __syncthreads();

    const int rIn  = warp & 3;      // row within chunk
    const int half = warp >> 2;     // 0/1: which 64-pair half of the row
    const int p0   = half * 64 + lane * 2;  // first of 2 pairs for this lane

    for (int c = 0; c < nChunks; ++c) {
        const int st = c & (STAGES - 1);
        const int ph = (c >> 2) & 1;
        mbar_wait(smem_u32(bar + st), ph);

        const int rAbs = r0 + c * ROWS_PER_CH + rIn;
        if (rAbs < r1) {
            const char* sp = s_stage + st * STAGE_BYTES;

            const int2   nb = *(const int2*)  (sp + ST_NB  + rIn * 512 + p0 * 4);
            const float2 mk = *(const float2*)(sp + ST_MK  + rIn * 512 + p0 * 4);
            const float* op = (const float*)  (sp + ST_OFF + rIn * 1536 + p0 * 12);
            const float ox0 = op[0], oy0 = op[1], oz0 = op[2];
            const float ox1 = op[3], oy1 = op[4], oz1 = op[5];

            const float4 pj0 = s_tab[nb.x];
            const float4 pj1 = s_tab[nb.y];
            const float4 pi  = s_tab[rAbs];

            float dx = pj0.x - pi.x, dy = pj0.y - pi.y, dz = pj0.z - pi.z;
            dx = fmaf(ox0, c00, fmaf(oy0, c10, fmaf(oz0, c20, dx)));
            dy = fmaf(ox0, c01, fmaf(oy0, c11, fmaf(oz0, c21, dy)));
            dz = fmaf(ox0, c02, fmaf(oy0, c12, fmaf(oz0, c22, dz)));
            const float d0 = (mk.x > 0.0f)
                ? sqrtf(fmaf(dx, dx, fmaf(dy, dy, dz * dz))) : 0.0f;

            float ex = pj1.x - pi.x, ey = pj1.y - pi.y, ez = pj1.z - pi.z;
            ex = fmaf(ox1, c00, fmaf(oy1, c10, fmaf(oz1, c20, ex)));
            ey = fmaf(ox1, c01, fmaf(oy1, c11, fmaf(oz1, c21, ey)));
            ez = fmaf(ox1, c02, fmaf(oy1, c12, fmaf(oz1, c22, ez)));
            const float d1 = (mk.y > 0.0f)
                ? sqrtf(fmaf(ex, ex, fmaf(ey, ey, ez * ez))) : 0.0f;

            __stcs((float2*)(out + ((size_t)b * N + rAbs) * TK + p0),
                   make_float2(d0, d1));
        }

        mbar_arrive(smem_u32(bar + STAGES + st));   // empty arrival (all threads)

        if (tid == 0) {
            const int j = c + STAGES - 1;           // next chunk to issue
            if (j < nChunks) {
                const int sj = j & (STAGES - 1);
                if (j >= STAGES)                     // stage previously used by chunk j-4
                    mbar_wait(smem_u32(bar + STAGES + sj), ((j - STAGES) >> 2) & 1);
                const int rBase = r0 + j * ROWS_PER_CH;
                const int rows  = min(ROWS_PER_CH, r1 - rBase);
                const uint32_t fb = smem_u32(bar + sj);
                mbar_expect_tx(fb, (uint32_t)rows * 2560u);
                const size_t g = (size_t)b * N + rBase;
                const uint32_t dst = stage_a + sj * STAGE_BYTES;
                bulk_g2s(dst + ST_NB,  neighbors + g * TK,     rows * 512,  fb);
                bulk_g2s(dst + ST_MK,  mask      + g * TK,     rows * 512,  fb);
                bulk_g2s(dst + ST_OFF, offsets   + g * TK * 3, rows * 1536, fb);
            }
        }
    }
}

// ---------------- generic smem kernel (shape variants) ----------------
__global__ __launch_bounds__(256, 3)
void pairwise_smem_kernel(const float*  __restrict__ positions,
                          const int*    __restrict__ neighbors,
                          const float*  __restrict__ mask,
                          const float*  __restrict__ cell,
                          const float*  __restrict__ offsets,
                          float*        __restrict__ out,
                          int N, int K, int rowsPer)
{
    extern __shared__ float4 s_tab[];
    const int b = blockIdx.y;

    const float* pb = positions + (size_t)b * N * 3;
    for (int i = threadIdx.x; i < N; i += blockDim.x)
        s_tab[i] = make_float4(__ldg(&pb[i * 3 + 0]),
                               __ldg(&pb[i * 3 + 1]),
                               __ldg(&pb[i * 3 + 2]), 0.0f);

    const float* cbp = cell + b * 9;
    const float c00 = __ldg(&cbp[0]), c01 = __ldg(&cbp[1]), c02 = __ldg(&cbp[2]);
    const float c10 = __ldg(&cbp[3]), c11 = __ldg(&cbp[4]), c12 = __ldg(&cbp[5]);
    const float c20 = __ldg(&cbp[6]), c21 = __ldg(&cbp[7]), c22 = __ldg(&cbp[8]);
    __syncthreads();

    const int warp = threadIdx.x >> 5;
    const int lane = threadIdx.x & 31;
    const int r0 = blockIdx.x * rowsPer;
    const int r1 = min(r0 + rowsPer, N);

    for (int r = r0 + warp; r < r1; r += 8) {
        const float4 pi4 = s_tab[r];
        for (int k0 = lane * 4; k0 < K; k0 += 128) {
            const long base = ((long)b * N + r) * (long)K + k0;
            const int4   nb4 = __ldcs((const int4*)  (neighbors + base));
            const float4 mk4 = __ldcs((const float4*)(mask      + base));
            const float* offp = offsets + base * 3;
            const float4 o0 = __ldcs((const float4*)(offp + 0));
            const float4 o1 = __ldcs((const float4*)(offp + 4));
            const float4 o2 = __ldcs((const float4*)(offp + 8));
            const int   jj[4] = { nb4.x, nb4.y, nb4.z, nb4.w };
            const float ox[4] = { o0.x, o0.w, o1.z, o2.y };
            const float oy[4] = { o0.y, o1.x, o1.w, o2.z };
            const float oz[4] = { o0.z, o1.y, o2.x, o2.w };
            const float mm[4] = { mk4.x, mk4.y, mk4.z, mk4.w };
            float4 pj[4];
#pragma unroll
            for (int t = 0; t < 4; ++t) pj[t] = s_tab[jj[t]];
            float res[4];
#pragma unroll
            for (int t = 0; t < 4; ++t) {
                float dx = pj[t].x - pi4.x;
                float dy = pj[t].y - pi4.y;
                float dz = pj[t].z - pi4.z;
                dx = fmaf(ox[t], c00, fmaf(oy[t], c10, fmaf(oz[t], c20, dx)));
                dy = fmaf(ox[t], c01, fmaf(oy[t], c11, fmaf(oz[t], c21, dy)));
                dz = fmaf(ox[t], c02, fmaf(oy[t], c12, fmaf(oz[t], c22, dz)));
                res[t] = (mm[t] > 0.0f)
                       ? sqrtf(fmaf(dx, dx, fmaf(dy, dy, dz * dz))) : 0.0f;
            }
            __stcs((float4*)(out + base),
                   make_float4(res[0], res[1], res[2], res[3]));
        }
    }
}

// ---------------- scalar fallback (oversized N) ----------------
__global__ __launch_bounds__(256)
void pairwise_fallback_kernel(const float* __restrict__ positions,
                              const int*   __restrict__ neighbors,
                              const float* __restrict__ mask,
                              const float* __restrict__ cell,
                              const float* __restrict__ offsets,
                              float*       __restrict__ out,
                              int N, int K, long total)
{
    long idx = (long)blockIdx.x * blockDim.x + threadIdx.x;
    if (idx >= total) return;
    const long row = idx / K;
    const int  k   = (int)(idx - row * K);
    const int  b   = (int)(row / N);

    const float pix = positions[row * 3 + 0];
    const float piy = positions[row * 3 + 1];
    const float piz = positions[row * 3 + 2];
    const int j = neighbors[idx];
    const float* pj = positions + ((size_t)b * N + j) * 3;
    const float* cbp = cell + b * 9;
    const float* op  = offsets + idx * 3;
    float dx = pj[0] - pix, dy = pj[1] - piy, dz = pj[2] - piz;
    dx = fmaf(op[0], cbp[0], fmaf(op[1], cbp[3], fmaf(op[2], cbp[6], dx)));
    dy = fmaf(op[0], cbp[1], fmaf(op[1], cbp[4], fmaf(op[2], cbp[7], dy)));
    dz = fmaf(op[0], cbp[2], fmaf(op[1], cbp[5], fmaf(op[2], cbp[8], dz)));
    out[idx] = (mask[idx] > 0.0f)
             ? sqrtf(fmaf(dx, dx, fmaf(dy, dy, dz * dz))) : 0.0f;
}

extern "C" void kernel_launch(void* const* d_in, const int* in_sizes, int n_in,
                              void* d_out, int out_size)
{
    const float* positions = (const float*)d_in[0];
    const int*   neighbors = (const int*)  d_in[1];
    const float* mask      = (const float*)d_in[2];
    const float* cell      = (const float*)d_in[3];
    const float* offsets   = (const float*)d_in[4];
    float*       out       = (float*)d_out;

    const int B      = in_sizes[3] / 9;
    const int n_rows = in_sizes[0] / 3;      // B*N
    const int N      = n_rows / B;
    const int K      = in_sizes[1] / n_rows;

    const size_t tabBytes = (size_t)N * sizeof(float4);

    if (K == 128 && tabBytes <= 65536) {
        const size_t smem = tabBytes + STAGES * STAGE_BYTES + 2 * STAGES * 8;
        static bool attr_set = false;
        if (!attr_set) {
            cudaFuncSetAttribute(pairwise_tma_kernel,
                                 cudaFuncAttributeMaxDynamicSharedMemorySize,
                                 (int)(65536 + STAGES * STAGE_BYTES + 2 * STAGES * 8));
            attr_set = true;
        }
        int S = 296 / B; if (S < 1) S = 1;               // 2 CTAs/SM x 148
        int rowsPer = (N + S - 1) / S;
        rowsPer = (rowsPer + ROWS_PER_CH - 1) & ~(ROWS_PER_CH - 1);
        S = (N + rowsPer - 1) / rowsPer;                 // trim empty CTAs
        dim3 grid(S, B);
        pairwise_tma_kernel<<<grid, 256, smem>>>(positions, neighbors, mask,
                                                 cell, offsets, out, N, rowsPer);
    } else if (tabBytes <= 65536) {
        static bool attr_set2 = false;
        if (!attr_set2) {
            cudaFuncSetAttribute(pairwise_smem_kernel,
                                 cudaFuncAttributeMaxDynamicSharedMemorySize, 65536);
            attr_set2 = true;
        }
        int S = 444 / B; if (S < 1) S = 1;
        const int rowsPer = (N + S - 1) / S;
        dim3 grid(S, B);
        pairwise_smem_kernel<<<grid, 256, tabBytes>>>(positions, neighbors, mask,
                                                      cell, offsets, out, N, K, rowsPer);
    } else {
        const long total = (long)n_rows * K;
        const int grid = (int)((total + 255) / 256);
        pairwise_fallback_kernel<<<grid, 256>>>(positions, neighbors, mask,
                                                cell, offsets, out, N, K, total);
    }
}

// round 7
// speedup vs baseline: 1.2546x; 1.2546x over previous
#include <cuda_runtime.h>
#include <cuda_bf16.h>
#include <cstdint>

// PairwiseRepresentation: masked periodic pairwise distances.
//   positions      [B,N,3]   f32
//   neighbors      [B,N,K]   i32
//   neighbor_mask  [B,N,K]   f32
//   cell           [B,3,3]   f32
//   cell_offsets   [B,N,K,3] f32
//   out            [B,N,K]   f32
//
// R7 consolidation: fused table fill (R4's win) + 256-thr/3-CTA-per-SM simple
// body (best per-kernel config, R3/R5) with NO row unroll (R5's unroll raised
// regs 72->80 for zero gain). Table fill vectorized with float4 loads.
// Streams: register-direct LDG.128 .cs (beat both TMA-bulk and every staging
// variant). Gathers: random LDS.128 from the 64KB per-batch smem table.

#define MAX_ROWS (16 * 4096)
__device__ float4 g_pos4[MAX_ROWS];   // scratch for the oversized-N fallback

__global__ __launch_bounds__(256)
void pad_positions_kernel(const float* __restrict__ positions, int n_rows)
{
    int i = blockIdx.x * blockDim.x + threadIdx.x;
    if (i < n_rows && i < MAX_ROWS) {
        g_pos4[i] = make_float4(positions[i * 3 + 0],
                                positions[i * 3 + 1],
                                positions[i * 3 + 2], 0.0f);
    }
}

// ---------------- main kernel: fused fill + smem gather ----------------
__global__ __launch_bounds__(256, 3)
void pairwise_smem_kernel(const float*  __restrict__ positions,
                          const int*    __restrict__ neighbors,
                          const float*  __restrict__ mask,
                          const float*  __restrict__ cell,
                          const float*  __restrict__ offsets,
                          float*        __restrict__ out,
                          int N, int K, int rowsPer)
{
    extern __shared__ float4 s_tab[];          // N float4s (64KB for N=4096)
    float* s_tabf = (float*)s_tab;

    const int b = blockIdx.y;

    // Vectorized fused pad + fill: read positions[b] as float4s (3N/4 of them),
    // scatter the 4 floats into the padded table (smem float idx = 4*row + c).
    {
        const float4* pb4   = (const float4*)(positions + (size_t)b * N * 3);
        const int     nVec  = (N * 3) / 4;     // N*3 divisible by 4 when N%4==0
        for (int t = threadIdx.x; t < nVec; t += blockDim.x) {
            const float4 v = __ldg(&pb4[t]);
            const int g = 4 * t;               // global float index
#pragma unroll
            for (int j = 0; j < 4; ++j) {
                const int gf  = g + j;
                const int row = gf / 3;
                const int c   = gf - row * 3;
                s_tabf[4 * row + c] = (&v.x)[j];
            }
        }
        // tail (N*3 not divisible by 4)
        for (int gf = nVec * 4 + threadIdx.x; gf < N * 3; gf += blockDim.x) {
            const int row = gf / 3;
            const int c   = gf - row * 3;
            s_tabf[4 * row + c] = __ldg(positions + (size_t)b * N * 3 + gf);
        }
    }

    // Per-batch cell matrix -> registers.
    const float* cbp = cell + b * 9;
    const float c00 = __ldg(&cbp[0]), c01 = __ldg(&cbp[1]), c02 = __ldg(&cbp[2]);
    const float c10 = __ldg(&cbp[3]), c11 = __ldg(&cbp[4]), c12 = __ldg(&cbp[5]);
    const float c20 = __ldg(&cbp[6]), c21 = __ldg(&cbp[7]), c22 = __ldg(&cbp[8]);

    __syncthreads();

    const int warp = threadIdx.x >> 5;         // 0..7
    const int lane = threadIdx.x & 31;

    const int r0 = blockIdx.x * rowsPer;
    const int r1 = min(r0 + rowsPer, N);

    for (int r = r0 + warp; r < r1; r += 8) {
        const float4 pi4 = s_tab[r];
        const float pix = pi4.x, piy = pi4.y, piz = pi4.z;

        for (int k0 = lane * 4; k0 < K; k0 += 128) {
            const long base = ((long)b * N + r) * (long)K + k0;

            const int4   nb4 = __ldcs((const int4*)  (neighbors + base));
            const float4 mk4 = __ldcs((const float4*)(mask      + base));

            const float* offp = offsets + base * 3;
            const float4 o0 = __ldcs((const float4*)(offp + 0));
            const float4 o1 = __ldcs((const float4*)(offp + 4));
            const float4 o2 = __ldcs((const float4*)(offp + 8));

            const int   jj[4] = { nb4.x, nb4.y, nb4.z, nb4.w };
            const float ox[4] = { o0.x, o0.w, o1.z, o2.y };
            const float oy[4] = { o0.y, o1.x, o1.w, o2.z };
            const float oz[4] = { o0.z, o1.y, o2.x, o2.w };
            const float mm[4] = { mk4.x, mk4.y, mk4.z, mk4.w };

            float4 pj[4];
#pragma unroll
            for (int t = 0; t < 4; ++t) pj[t] = s_tab[jj[t]];

            float res[4];
#pragma unroll
            for (int t = 0; t < 4; ++t) {
                float dx = pj[t].x - pix;
                float dy = pj[t].y - piy;
                float dz = pj[t].z - piz;
                dx = fmaf(ox[t], c00, fmaf(oy[t], c10, fmaf(oz[t], c20, dx)));
                dy = fmaf(ox[t], c01, fmaf(oy[t], c11, fmaf(oz[t], c21, dy)));
                dz = fmaf(ox[t], c02, fmaf(oy[t], c12, fmaf(oz[t], c22, dz)));
                res[t] = (mm[t] > 0.0f)
                       ? sqrtf(fmaf(dx, dx, fmaf(dy, dy, dz * dz))) : 0.0f;
            }

            __stcs((float4*)(out + base),
                   make_float4(res[0], res[1], res[2], res[3]));
        }
    }
}

// ---------------- scalar fallback (oversized N) ----------------
__global__ __launch_bounds__(256)
void pairwise_fallback_kernel(const float* __restrict__ positions,
                              const int*   __restrict__ neighbors,
                              const float* __restrict__ mask,
                              const float* __restrict__ cell,
                              const float* __restrict__ offsets,
                              float*       __restrict__ out,
                              int N, int K, long total)
{
    long idx = (long)blockIdx.x * blockDim.x + threadIdx.x;
    if (idx >= total) return;
    const long row = idx / K;
    const int  b   = (int)(row / N);

    const float pix = positions[row * 3 + 0];
    const float piy = positions[row * 3 + 1];
    const float piz = positions[row * 3 + 2];
    const int j = neighbors[idx];
    const float* pj  = positions + ((size_t)b * N + j) * 3;
    const float* cbp = cell + b * 9;
    const float* op  = offsets + idx * 3;
    float dx = pj[0] - pix, dy = pj[1] - piy, dz = pj[2] - piz;
    dx = fmaf(op[0], cbp[0], fmaf(op[1], cbp[3], fmaf(op[2], cbp[6], dx)));
    dy = fmaf(op[0], cbp[1], fmaf(op[1], cbp[4], fmaf(op[2], cbp[7], dy)));
    dz = fmaf(op[0], cbp[2], fmaf(op[1], cbp[5], fmaf(op[2], cbp[8], dz)));
    out[idx] = (mask[idx] > 0.0f)
             ? sqrtf(fmaf(dx, dx, fmaf(dy, dy, dz * dz))) : 0.0f;
}

extern "C" void kernel_launch(void* const* d_in, const int* in_sizes, int n_in,
                              void* d_out, int out_size)
{
    const float* positions = (const float*)d_in[0];
    const int*   neighbors = (const int*)  d_in[1];
    const float* mask      = (const float*)d_in[2];
    const float* cell      = (const float*)d_in[3];
    const float* offsets   = (const float*)d_in[4];
    float*       out       = (float*)d_out;

    const int B      = in_sizes[3] / 9;
    const int n_rows = in_sizes[0] / 3;      // B*N
    const int N      = n_rows / B;
    const int K      = in_sizes[1] / n_rows;

    const size_t tabBytes = (size_t)N * sizeof(float4);

    if (tabBytes <= 65536 && (K % 4) == 0) {
        static bool attr_set = false;
        if (!attr_set) {
            cudaFuncSetAttribute(pairwise_smem_kernel,
                                 cudaFuncAttributeMaxDynamicSharedMemorySize, 65536);
            attr_set = true;
        }
        // 3 CTAs/SM x 148 SMs = 444 slots; S segments per batch.
        int S = 444 / B; if (S < 1) S = 1;
        const int rowsPer = (N + S - 1) / S;
        S = (N + rowsPer - 1) / rowsPer;     // trim empty CTAs
        dim3 grid(S, B);
        pairwise_smem_kernel<<<grid, 256, tabBytes>>>(positions, neighbors, mask,
                                                      cell, offsets, out,
                                                      N, K, rowsPer);
    } else {
        const long total = (long)n_rows * K;
        const int grid = (int)((total + 255) / 256);
        pairwise_fallback_kernel<<<grid, 256>>>(positions, neighbors, mask,
                                                cell, offsets, out, N, K, total);
    }
}